// round 1
// baseline (speedup 1.0000x reference)
#include <cuda_runtime.h>
#include <cstddef>

// Problem constants (from reference setup_inputs)
#define ON 2
#define OC 256
#define OT 16
#define OH 56
#define OW 56
#define OUTB 16      // OUT bins per side
#define GRIDS 2      // sampling grid per bin side
#define RSCALE (1.0f/16.0f)
#define C_PER_BLOCK 16

// One block handles (n, k, t, c-chunk). 256 threads = 16x16 output bins.
// Each thread computes its 2x2 sample points (coords + bilinear weights,
// invariant across c and t) once into registers, then loops channels doing
// 16 gathers + 16 FFMAs per channel. Mask and the grid-mean (x0.25) are
// folded into the weights.
__global__ __launch_bounds__(256) void roi_align_kernel(
    const float* __restrict__ feat,
    const float* __restrict__ rois,
    float* __restrict__ out,
    int K)
{
    const int n_cchunk = OC / C_PER_BLOCK;
    int b  = blockIdx.x;
    int cc = b % n_cchunk; b /= n_cchunk;
    int t  = b % OT;       b /= OT;
    int k  = b % K;        b /= K;
    int n  = b;

    const int tid = threadIdx.x;      // 0..255
    const int px  = tid & (OUTB - 1);
    const int py  = tid >> 4;

    const float* roi = rois + (size_t)(n * K + k) * 5;
    const float x1 = roi[1] * RSCALE - 0.5f;
    const float y1 = roi[2] * RSCALE - 0.5f;
    const float x2 = roi[3] * RSCALE - 0.5f;
    const float y2 = roi[4] * RSCALE - 0.5f;
    const float bw = (x2 - x1) * (1.0f / OUTB);
    const float bh = (y2 - y1) * (1.0f / OUTB);

    int   off[4][4];
    float w[4][4];
    #pragma unroll
    for (int gy = 0; gy < GRIDS; gy++) {
        const float Y = y1 + ((float)py + ((float)gy + 0.5f) / GRIDS) * bh;
        #pragma unroll
        for (int gx = 0; gx < GRIDS; gx++) {
            const float X = x1 + ((float)px + ((float)gx + 0.5f) / GRIDS) * bw;
            const int s = gy * 2 + gx;
            const bool valid = (Y > -1.0f) && (Y < (float)OH) &&
                               (X > -1.0f) && (X < (float)OW);
            const float Yc = fminf(fmaxf(Y, 0.0f), (float)(OH - 1));
            const float Xc = fminf(fmaxf(X, 0.0f), (float)(OW - 1));
            const int y0  = (int)Yc;            // Yc >= 0 -> trunc == floor
            const int x0  = (int)Xc;
            const int y1i = min(y0 + 1, OH - 1);
            const int x1i = min(x0 + 1, OW - 1);
            const float ly = Yc - (float)y0;
            const float lx = Xc - (float)x0;
            const float hy = 1.0f - ly;
            const float hx = 1.0f - lx;
            const float m = valid ? 0.25f : 0.0f;   // fold grid-mean into mask
            off[s][0] = y0  * OW + x0;
            off[s][1] = y0  * OW + x1i;
            off[s][2] = y1i * OW + x0;
            off[s][3] = y1i * OW + x1i;
            w[s][0] = hy * hx * m;
            w[s][1] = hy * lx * m;
            w[s][2] = ly * hx * m;
            w[s][3] = ly * lx * m;
        }
    }

    const int c0 = cc * C_PER_BLOCK;
    // Output base for this (n,t,k) at channel c0, bin tid.
    float* obase = out + ((size_t)((n * OT + t) * K + k) * OC + c0) * (OUTB * OUTB) + tid;
    const float* fbase = feat + ((size_t)(n * OC + c0) * OT + t) * (OH * OW);

    #pragma unroll 2
    for (int ci = 0; ci < C_PER_BLOCK; ci++) {
        const float* f = fbase + (size_t)ci * (OT * OH * OW);
        float acc = 0.0f;
        #pragma unroll
        for (int s = 0; s < 4; s++) {
            acc += f[off[s][0]] * w[s][0];
            acc += f[off[s][1]] * w[s][1];
            acc += f[off[s][2]] * w[s][2];
            acc += f[off[s][3]] * w[s][3];
        }
        obase[(size_t)ci * (OUTB * OUTB)] = acc;
    }
}

extern "C" void kernel_launch(void* const* d_in, const int* in_sizes, int n_in,
                              void* d_out, int out_size)
{
    const float* feat = (const float*)d_in[0];
    const float* rois = (const float*)d_in[1];
    // d_in[2] = entity_mask (unused by the reference output)

    const int K = in_sizes[1] / (ON * 5);   // 5 floats per roi
    float* out = (float*)d_out;

    const size_t roi_elems  = (size_t)ON * OT * K * OC * OUTB * OUTB;
    const size_t feat_bytes = (size_t)in_sizes[0] * sizeof(float);

    // RoIAlign gather
    const int grid = ON * K * OT * (OC / C_PER_BLOCK);
    roi_align_kernel<<<grid, 256>>>(feat, rois, out, K);

    // Tuple second element: verbatim feat passthrough (D2D memcpy node).
    cudaMemcpyAsync(out + roi_elems, feat, feat_bytes,
                    cudaMemcpyDeviceToDevice, 0);
}

// round 2
// speedup vs baseline: 1.1229x; 1.1229x over previous
#include <cuda_runtime.h>
#include <cstddef>

// Problem constants (from reference setup_inputs)
#define ON 2
#define OC 256
#define OT 16
#define OH 56
#define OW 56
#define OUTB 16      // OUT bins per side
#define GRIDS 2      // sampling grid per bin side
#define RSCALE (1.0f/16.0f)
#define C_PER_BLOCK 16

#define GATHER_BLOCKS (ON * 5 * OT * (OC / C_PER_BLOCK))   // 2560 for K=5
#define COPY_BLOCKS   2560
#define FEAT_ELEMS    ((size_t)ON * OC * OT * OH * OW)      // 25,690,112
#define FEAT_VEC4     (FEAT_ELEMS / 4)                      // 6,422,528
#define ROI_ELEMS     ((size_t)ON * OT * 5 * OC * OUTB * OUTB)

// Fused kernel: even blocks do the RoIAlign gather (L1-bound scattered loads),
// odd blocks do the feat passthrough copy (DRAM-bound float4 streaming).
// Interleaving by blockIdx parity keeps both resource classes busy in every
// wave instead of serializing a gather kernel then a memcpy.
__global__ __launch_bounds__(256) void roi_fused_kernel(
    const float* __restrict__ feat,
    const float* __restrict__ rois,
    float* __restrict__ out,
    int K)
{
    const int bid = blockIdx.x;
    const int tid = threadIdx.x;

    if (bid & 1) {
        // ---------------- copy role: out[roi_elems + i] = feat[i] ----------------
        const int cid = bid >> 1;                       // 0..COPY_BLOCKS-1
        const float4* __restrict__ src = (const float4*)feat;
        float4* __restrict__ dst = (float4*)(out + ROI_ELEMS);
        size_t idx = (size_t)cid * 256 + tid;
        const size_t stride = (size_t)COPY_BLOCKS * 256;
        for (; idx < FEAT_VEC4; idx += stride)
            dst[idx] = src[idx];
        return;
    }

    // ---------------- gather role: RoIAlign ----------------
    const int n_cchunk = OC / C_PER_BLOCK;
    int b  = bid >> 1;
    int cc = b % n_cchunk; b /= n_cchunk;
    int t  = b % OT;       b /= OT;
    int k  = b % K;        b /= K;
    int n  = b;

    const int px  = tid & (OUTB - 1);
    const int py  = tid >> 4;

    const float* roi = rois + (size_t)(n * K + k) * 5;
    const float x1 = roi[1] * RSCALE - 0.5f;
    const float y1 = roi[2] * RSCALE - 0.5f;
    const float x2 = roi[3] * RSCALE - 0.5f;
    const float y2 = roi[4] * RSCALE - 0.5f;
    const float bw = (x2 - x1) * (1.0f / OUTB);
    const float bh = (y2 - y1) * (1.0f / OUTB);

    int   off[4][4];
    float w[4][4];
    #pragma unroll
    for (int gy = 0; gy < GRIDS; gy++) {
        const float Y = y1 + ((float)py + ((float)gy + 0.5f) / GRIDS) * bh;
        #pragma unroll
        for (int gx = 0; gx < GRIDS; gx++) {
            const float X = x1 + ((float)px + ((float)gx + 0.5f) / GRIDS) * bw;
            const int s = gy * 2 + gx;
            const bool valid = (Y > -1.0f) && (Y < (float)OH) &&
                               (X > -1.0f) && (X < (float)OW);
            const float Yc = fminf(fmaxf(Y, 0.0f), (float)(OH - 1));
            const float Xc = fminf(fmaxf(X, 0.0f), (float)(OW - 1));
            const int y0  = (int)Yc;            // Yc >= 0 -> trunc == floor
            const int x0  = (int)Xc;
            const int y1i = min(y0 + 1, OH - 1);
            const int x1i = min(x0 + 1, OW - 1);
            const float ly = Yc - (float)y0;
            const float lx = Xc - (float)x0;
            const float hy = 1.0f - ly;
            const float hx = 1.0f - lx;
            const float m = valid ? 0.25f : 0.0f;   // fold grid-mean into mask
            off[s][0] = y0  * OW + x0;
            off[s][1] = y0  * OW + x1i;
            off[s][2] = y1i * OW + x0;
            off[s][3] = y1i * OW + x1i;
            w[s][0] = hy * hx * m;
            w[s][1] = hy * lx * m;
            w[s][2] = ly * hx * m;
            w[s][3] = ly * lx * m;
        }
    }

    const int c0 = cc * C_PER_BLOCK;
    float* obase = out + ((size_t)((n * OT + t) * K + k) * OC + c0) * (OUTB * OUTB) + tid;
    const float* fbase = feat + ((size_t)(n * OC + c0) * OT + t) * (OH * OW);

    #pragma unroll 2
    for (int ci = 0; ci < C_PER_BLOCK; ci++) {
        const float* f = fbase + (size_t)ci * (OT * OH * OW);
        float acc = 0.0f;
        #pragma unroll
        for (int s = 0; s < 4; s++) {
            acc += f[off[s][0]] * w[s][0];
            acc += f[off[s][1]] * w[s][1];
            acc += f[off[s][2]] * w[s][2];
            acc += f[off[s][3]] * w[s][3];
        }
        obase[(size_t)ci * (OUTB * OUTB)] = acc;
    }
}

extern "C" void kernel_launch(void* const* d_in, const int* in_sizes, int n_in,
                              void* d_out, int out_size)
{
    const float* feat = (const float*)d_in[0];
    const float* rois = (const float*)d_in[1];
    // d_in[2] = entity_mask (unused by the reference output)

    const int K = in_sizes[1] / (ON * 5);   // 5 floats per roi
    float* out = (float*)d_out;

    const int gather_blocks = ON * K * OT * (OC / C_PER_BLOCK);  // 2560 for K=5
    const int grid = gather_blocks + COPY_BLOCKS;                // interleaved roles

    roi_fused_kernel<<<grid, 256>>>(feat, rois, out, K);
}